// round 16
// baseline (speedup 1.0000x reference)
#include <cuda_runtime.h>
#include <math.h>
#include <stdint.h>

#define NTOK 200
#define CD   256
#define TD   128
#define NHH  8
#define DKK  32
#define DFFD 1024
#define ITER 4
#define NCT  (NTOK*CD*TD)
#define NC   (NTOK*CD)

#define OFF_EMBS   0
#define OFF_NODES  (1*NCT)
#define OFF_XLN    (2*NCT)
#define OFF_QKV    (3*NCT)             /* 3 NCT: [n][768][T] */
#define OFF_S      (6*NCT)
#define OFF_RET    (7*NCT)
#define OFF_O      (8*NCT)
#define OFF_KTRVTR (9*NCT)             /* 2 NCT: [n][512][T] */
#define OFF_H      (11*NCT)            /* 4 NCT tf32 */
#define OFF_KEVE   (15*NCT)            /* 8 NCT: 4 layers x [n][512][T] */
#define OFF_RELAY  (23*NCT)
#define OFF_KR     (OFF_RELAY+NC)
#define OFF_VR     (OFF_KR+NC)
#define OFF_QTR    (OFF_VR+NC)
#define OFF_KTRR   (OFF_QTR+NC)
#define OFF_VTRR   (OFF_KTRR+NC)
#define OFF_Z      (OFF_VTRR+NC)
#define OFF_RETT   (OFF_Z+NC)
#define OFF_OTR    (OFF_RETT+NC)
#define OFF_HTR    (OFF_OTR+NC)
#define OFF_MEAN   (OFF_HTR+NTOK*DFFD)
#define OFF_INV    (OFF_MEAN+256)

/* fragment-major tf32 weights */
#define SEGQ       (128*256)
#define LQKV       (6*SEGQ)
#define LRKV       (4*SEGQ)
#define LW1        (DFFD*CD)
#define LW2        (CD*DFFD)
#define OFF_QKVW   (OFF_INV+256)
#define OFF_RWKVW  (OFF_QKVW + LQKV*ITER)
#define OFF_W1T    (OFF_RWKVW + LRKV*ITER)
#define OFF_W2T    (OFF_W1T + LW1*ITER)
#define OFF_XLN_T  (OFF_W2T + LW2*ITER)
#define OFF_EMBS_T (OFF_XLN_T + NCT)
#define OFF_RET_T  (OFF_EMBS_T + NCT)
#define OFF_NODES_T (OFF_RET_T + NCT)
#define OFF_RELAYB (OFF_NODES_T + NCT)      /* second relay buffer */
#define BUF_TOTAL  (OFF_RELAYB + NC)

__device__ __align__(16) float g_buf[BUF_TOTAL];

__device__ __forceinline__ uint32_t f2tf32(float x) {
    uint32_t r;
    asm("cvt.rna.tf32.f32 %0, %1;" : "=r"(r) : "f"(x));
    return r;
}

#define MMA_TF32(C, A, B)                                                     \
    asm volatile("mma.sync.aligned.m16n8k8.row.col.f32.tf32.tf32.f32 "        \
                 "{%0,%1,%2,%3}, {%4,%5,%6,%7}, {%8,%9}, {%0,%1,%2,%3};\n"    \
                 : "+f"((C)[0]), "+f"((C)[1]), "+f"((C)[2]), "+f"((C)[3])     \
                 : "r"((A)[0]), "r"((A)[1]), "r"((A)[2]), "r"((A)[3]),        \
                   "r"((B)[0]), "r"((B)[1]));

#define CP16(daddr, src)                                                      \
    asm volatile("cp.async.cg.shared.global [%0], [%1], 16;"                  \
                 :: "r"(daddr), "l"(src))
#define CP_COMMIT asm volatile("cp.async.commit_group;")
#define CP_WAIT(N) asm volatile("cp.async.wait_group %0;" :: "n"(N))

// ---------------------------------------------------------------------------
// Convert W (fp32 [layer][O][Cin]) to fragment-major tf32 at dst offset.
// ---------------------------------------------------------------------------
__global__ void conv_w_frag(const float* __restrict__ W, uint32_t* __restrict__ Wt,
                            int O, int Cin, size_t dl, size_t doff)
{
    size_t sbase = (size_t)blockIdx.y * O * Cin;
    size_t dbase = (size_t)blockIdx.y * dl + doff;
    int idx = blockIdx.x * 256 + threadIdx.x;
    if (idx >= O * Cin) return;
    int NCH = Cin >> 5;
    int j = idx & 3, sl = (idx >> 2) & 31, f = (idx >> 7) & 31;
    int rest = idx >> 12;
    int c = rest % NCH, ob = rest / NCH;
    int r = ob * 128 + (f >> 2) * 16 + (sl >> 2) + ((j & 1) << 3);
    int col = c * 32 + (f & 3) * 8 + (sl & 3) + ((j >> 1) << 2);
    Wt[dbase + idx] = f2tf32(W[sbase + (size_t)r * Cin + col]);
}

// ---------------------------------------------------------------------------
// prep
// ---------------------------------------------------------------------------
__global__ void prep_kernel(const float* __restrict__ data,
                            float* __restrict__ embs, uint32_t* __restrict__ embs_t,
                            float* __restrict__ relay)
{
    int n = blockIdx.x;
    int b = n / 25, v = n % 25;
    int c = blockIdx.y * 8 + threadIdx.y;
    int tx = threadIdx.x;
    const float* src = data + (((size_t)b * CD + c) * 25 + v) * TD;
    size_t dof = ((size_t)n * CD + c) * TD;
    float s = 0.f;
#pragma unroll
    for (int j = 0; j < 4; j++) {
        int t = tx + 32 * j;
        float x = src[t];
        embs[dof + t] = x;
        embs_t[dof + t] = f2tf32(x);
        s += x;
    }
#pragma unroll
    for (int o = 16; o > 0; o >>= 1) s += __shfl_xor_sync(0xffffffffu, s, o);
    if (tx == 0) relay[n * CD + c] = s * (1.0f / 128.0f);
}

// ---------------------------------------------------------------------------
// LayerNorm; writes fp32 + tf32. grid (NTOK,4), block (32,8)
// ---------------------------------------------------------------------------
__global__ void ln_kernel(const float* __restrict__ X, const float* __restrict__ g,
                          const float* __restrict__ b, float* __restrict__ Y,
                          uint32_t* __restrict__ Yt)
{
    int n = blockIdx.x;
    int t = blockIdx.y * 32 + threadIdx.x;
    int tx = threadIdx.x, ty = threadIdx.y;
    float x[32];
    float s1 = 0.f, s2 = 0.f;
#pragma unroll
    for (int j = 0; j < 32; j++) {
        int c = ty + j * 8;
        x[j] = X[((size_t)n * CD + c) * TD + t];
        s1 += x[j];
        s2 += x[j] * x[j];
    }
    __shared__ float sm1[8][32], sm2[8][32], smean[32], sinv[32];
    sm1[ty][tx] = s1; sm2[ty][tx] = s2;
    __syncthreads();
    if (ty == 0) {
        float a = 0.f, bb = 0.f;
#pragma unroll
        for (int qy = 0; qy < 8; qy++) { a += sm1[qy][tx]; bb += sm2[qy][tx]; }
        float m = a * (1.0f / 256.0f);
        float var = bb * (1.0f / 256.0f) - m * m;
        smean[tx] = m;
        sinv[tx] = rsqrtf(var + 1e-6f);
    }
    __syncthreads();
    float m = smean[tx], inv = sinv[tx];
#pragma unroll
    for (int j = 0; j < 32; j++) {
        int c = ty + j * 8;
        float vv = (x[j] - m) * inv * g[c] + b[c];
        size_t off = ((size_t)n * CD + c) * TD + t;
        Y[off] = vv;
        Yt[off] = f2tf32(vv);
    }
}

// ---------------------------------------------------------------------------
// TF32 GEMM, pre-converted operands + cp.async 3-stage pipeline.
// ---------------------------------------------------------------------------
#define XS_STR   132
#define WF_U32   (32 * 128)
#define BUFU     (WF_U32 + 32 * XS_STR)
#define GEMM_SMEM (3 * BUFU * 4)

template <int EPI, int NSEG>
__global__ __launch_bounds__(256, 2)
void gemm_pre(const uint32_t* __restrict__ Wt, const float* __restrict__ b0,
              const float* __restrict__ b1, const float* __restrict__ b2,
              const uint32_t* __restrict__ Xt, void* __restrict__ Yout,
              const float* __restrict__ Res, int O, int Cin,
              size_t wl, size_t yl)
{
    extern __shared__ __align__(16) uint32_t smem_dyn[];
    uint32_t smem_base = (uint32_t)__cvta_generic_to_shared(smem_dyn);

    int n = blockIdx.y;
    int z = blockIdx.z;
    int nchunks = Cin >> 5;
    const uint32_t* Wblk = Wt + (size_t)z * wl + (size_t)blockIdx.x * nchunks * WF_U32;
    const uint32_t* Xn = Xt + (size_t)n * Cin * TD;
    int tid = threadIdx.x;
    int lane = tid & 31, wid = tid >> 5;
    int warp_o = wid >> 2, warp_t = wid & 3;
    int g = lane >> 2, q = lane & 3;

#define ISSUE(c)                                                              \
    do {                                                                      \
        int bsel = (c) % 3;                                                   \
        uint32_t wb = smem_base + bsel * (BUFU * 4);                          \
        uint32_t xb = wb + WF_U32 * 4;                                        \
        const uint32_t* wsrc = Wblk + (size_t)(c) * WF_U32;                   \
        const uint32_t* xsrc = Xn + (size_t)(c) * 32 * TD;                    \
        _Pragma("unroll")                                                     \
        for (int r = 0; r < 4; r++) {                                         \
            int i = tid + 256 * r;                                            \
            CP16(wb + (uint32_t)i * 16, wsrc + i * 4);                        \
            int k = i >> 5, c4 = i & 31;                                      \
            CP16(xb + (uint32_t)(k * XS_STR + c4 * 4) * 4,                    \
                 xsrc + (size_t)k * TD + c4 * 4);                             \
        }                                                                     \
        CP_COMMIT;                                                            \
    } while (0)

    ISSUE(0);
    if (nchunks > 1) ISSUE(1);

    float acc[4][4][4];
#pragma unroll
    for (int m = 0; m < 4; m++)
#pragma unroll
        for (int nf = 0; nf < 4; nf++)
#pragma unroll
            for (int j = 0; j < 4; j++) acc[m][nf][j] = 0.f;

    int cidx = warp_t * 32 + g;
    for (int c = 0; c < nchunks; c++) {
        if (c + 1 < nchunks) { CP_WAIT(1); } else { CP_WAIT(0); }
        __syncthreads();
        if (c + 2 < nchunks) ISSUE(c + 2);

        const uint32_t* Wb = smem_dyn + (c % 3) * BUFU;
        const uint32_t* Xb = Wb + WF_U32;
#pragma unroll
        for (int kt = 0; kt < 4; kt++) {
            uint32_t a[4][4], b[4][2];
#pragma unroll
            for (int m = 0; m < 4; m++) {
                int f = (warp_o * 4 + m) * 4 + kt;
                *(uint4*)a[m] = *(const uint4*)&Wb[f * 128 + lane * 4];
            }
            const uint32_t* xrow0 = &Xb[(kt * 8 + q) * XS_STR + cidx];
            const uint32_t* xrow1 = xrow0 + 4 * XS_STR;
#pragma unroll
            for (int nf = 0; nf < 4; nf++) {
                b[nf][0] = xrow0[nf * 8];
                b[nf][1] = xrow1[nf * 8];
            }
#pragma unroll
            for (int m = 0; m < 4; m++)
#pragma unroll
                for (int nf = 0; nf < 4; nf++)
                    MMA_TF32(acc[m][nf], a[m], b[nf]);
        }
    }
#undef ISSUE

#pragma unroll
    for (int m = 0; m < 4; m++) {
        int obase = blockIdx.x * 128 + warp_o * 64 + m * 16 + g;
#pragma unroll
        for (int r = 0; r < 2; r++) {
            int o = obase + r * 8;
            float bs;
            if (NSEG == 1) {
                bs = b0[o];
            } else {
                int seg = o >> 8;
                const float* bp = (seg == 0) ? b0 : (seg == 1 ? b1 : b2);
                bs = bp[z * 256 + (o & 255)];
            }
            size_t rowoff = (size_t)z * yl + ((size_t)n * O + o) * TD;
#pragma unroll
            for (int nf = 0; nf < 4; nf++) {
                int t = warp_t * 32 + nf * 8 + q * 2;
                float v0 = acc[m][nf][r * 2 + 0] + bs;
                float v1 = acc[m][nf][r * 2 + 1] + bs;
                if (EPI == 1) {
                    v0 = fmaxf(v0, 0.f); v1 = fmaxf(v1, 0.f);
                    uint2 uu;
                    uu.x = f2tf32(v0); uu.y = f2tf32(v1);
                    *(uint2*)((uint32_t*)Yout + rowoff + t) = uu;
                } else {
                    if (EPI == 2) {
                        float2 rr = *(const float2*)(Res + rowoff + t);
                        v0 += rr.x; v1 += rr.y;
                    }
                    *(float2*)((float*)Yout + rowoff + t) = make_float2(v0, v1);
                }
            }
        }
    }
}

// ---------------------------------------------------------------------------
// Small GEMM over [N, Cin] tokens (relay path, fp32). Single weight/out.
// ---------------------------------------------------------------------------
template <int EPI>
__global__ __launch_bounds__(256)
void gemm_nc(const float* __restrict__ W, const float* __restrict__ bias,
             const float* __restrict__ X, float* __restrict__ Y,
             const float* __restrict__ Res, int O, int Cin)
{
    int o0 = blockIdx.x * 64;
    int n0 = blockIdx.y * 32;
    int tid = threadIdx.x;
    int tx = tid & 31, ty = tid >> 5;

    __shared__ float Ws[32][64];
    __shared__ float Xs[32][33];

    float acc[8];
#pragma unroll
    for (int i = 0; i < 8; i++) acc[i] = 0.f;

    for (int k0 = 0; k0 < Cin; k0 += 32) {
#pragma unroll
        for (int r = 0; r < 2; r++) {
            int idx = tid + 256 * r;
            int o = idx >> 3, kq = idx & 7;
            float4 w4 = *(const float4*)(W + (size_t)(o0 + o) * Cin + k0 + kq * 4);
            Ws[kq * 4 + 0][o] = w4.x;
            Ws[kq * 4 + 1][o] = w4.y;
            Ws[kq * 4 + 2][o] = w4.z;
            Ws[kq * 4 + 3][o] = w4.w;
        }
        {
            int nn = tid >> 3, kq = tid & 7;
            int n = n0 + nn;
            float4 x4 = make_float4(0.f, 0.f, 0.f, 0.f);
            if (n < NTOK) x4 = *(const float4*)(X + (size_t)n * Cin + k0 + kq * 4);
            Xs[kq * 4 + 0][nn] = x4.x;
            Xs[kq * 4 + 1][nn] = x4.y;
            Xs[kq * 4 + 2][nn] = x4.z;
            Xs[kq * 4 + 3][nn] = x4.w;
        }
        __syncthreads();
#pragma unroll
        for (int kk = 0; kk < 32; kk++) {
            float bv = Xs[kk][tx];
#pragma unroll
            for (int i = 0; i < 8; i++) acc[i] += Ws[kk][ty * 8 + i] * bv;
        }
        __syncthreads();
    }

    int n = n0 + tx;
    if (n < NTOK) {
#pragma unroll
        for (int i = 0; i < 8; i++) {
            int o = o0 + ty * 8 + i;
            float val = acc[i] + bias[o];
            if (EPI == 1) val = fmaxf(val, 0.f);
            if (EPI == 2) val += Res[(size_t)n * O + o];
            Y[(size_t)n * O + o] = val;
        }
    }
}

// ---------------------------------------------------------------------------
// Segmented small GEMM: up to 3 weight sets of [256][Cin] with own bias/out.
// grid (nseg*4, 7). Per-64-o block arithmetic identical to gemm_nc.
// ---------------------------------------------------------------------------
__global__ __launch_bounds__(256)
void gemm_nc_seg(const float* __restrict__ w0, const float* __restrict__ w1,
                 const float* __restrict__ w2,
                 const float* __restrict__ b0, const float* __restrict__ b1,
                 const float* __restrict__ b2,
                 const float* __restrict__ X,
                 float* __restrict__ y0, float* __restrict__ y1,
                 float* __restrict__ y2, int Cin)
{
    int o0g = blockIdx.x * 64;
    int seg = o0g >> 8;
    const float* W = (seg == 0) ? w0 : (seg == 1 ? w1 : w2);
    const float* bias = (seg == 0) ? b0 : (seg == 1 ? b1 : b2);
    float* Y = (seg == 0) ? y0 : (seg == 1 ? y1 : y2);
    int o0 = o0g & 255;
    int n0 = blockIdx.y * 32;
    int tid = threadIdx.x;
    int tx = tid & 31, ty = tid >> 5;

    __shared__ float Ws[32][64];
    __shared__ float Xs[32][33];

    float acc[8];
#pragma unroll
    for (int i = 0; i < 8; i++) acc[i] = 0.f;

    for (int k0 = 0; k0 < Cin; k0 += 32) {
#pragma unroll
        for (int r = 0; r < 2; r++) {
            int idx = tid + 256 * r;
            int o = idx >> 3, kq = idx & 7;
            float4 w4 = *(const float4*)(W + (size_t)(o0 + o) * Cin + k0 + kq * 4);
            Ws[kq * 4 + 0][o] = w4.x;
            Ws[kq * 4 + 1][o] = w4.y;
            Ws[kq * 4 + 2][o] = w4.z;
            Ws[kq * 4 + 3][o] = w4.w;
        }
        {
            int nn = tid >> 3, kq = tid & 7;
            int n = n0 + nn;
            float4 x4 = make_float4(0.f, 0.f, 0.f, 0.f);
            if (n < NTOK) x4 = *(const float4*)(X + (size_t)n * Cin + k0 + kq * 4);
            Xs[kq * 4 + 0][nn] = x4.x;
            Xs[kq * 4 + 1][nn] = x4.y;
            Xs[kq * 4 + 2][nn] = x4.z;
            Xs[kq * 4 + 3][nn] = x4.w;
        }
        __syncthreads();
#pragma unroll
        for (int kk = 0; kk < 32; kk++) {
            float bv = Xs[kk][tx];
#pragma unroll
            for (int i = 0; i < 8; i++) acc[i] += Ws[kk][ty * 8 + i] * bv;
        }
        __syncthreads();
    }

    int n = n0 + tx;
    if (n < NTOK) {
#pragma unroll
        for (int i = 0; i < 8; i++) {
            int o = o0 + ty * 8 + i;
            Y[(size_t)n * 256 + o] = acc[i] + bias[o];
        }
    }
}

// ---------------------------------------------------------------------------
// tju attention. qkv: [n][768][T]; keve: [n][512][T]. grid NTOK*NHH, block 128.
// ---------------------------------------------------------------------------
__global__ void attn_tju(const float* __restrict__ qkv, const float* __restrict__ keve,
                         const float* __restrict__ kr, const float* __restrict__ vr,
                         const float* __restrict__ xln, float* __restrict__ sout)
{
    int nh = blockIdx.x;
    int n = nh >> 3, h = nh & 7;
    int t = threadIdx.x;
    int rbase = n * CD + h * DKK;
    size_t base = (size_t)rbase * TD;
    size_t bq = ((size_t)n * 768 + h * DKK) * TD;
    size_t bke = ((size_t)n * 512 + h * DKK) * TD;
    const size_t KOFF = (size_t)256 * TD, VOFF = (size_t)512 * TD;

    float l0 = 0.f, l1 = 0.f, l2 = 0.f, l3 = 0.f, l4 = 0.f;
#pragma unroll 8
    for (int d = 0; d < DKK; d++) {
        size_t oq = bq + (size_t)d * TD + t;
        float qd = qkv[oq];
        float kc = qkv[oq + KOFF];
        float km = (t > 0) ? qkv[oq + KOFF - 1] : 0.f;
        float kp = (t < TD - 1) ? qkv[oq + KOFF + 1] : 0.f;
        l0 += qd * km;
        l1 += qd * kc;
        l2 += qd * kp;
        l3 += qd * keve[bke + (size_t)d * TD + t];
        l4 += qd * kr[rbase + d];
    }
    const float sc = 0.17677669529663687f;
    l0 *= sc; l1 *= sc; l2 *= sc; l3 *= sc; l4 *= sc;
    float m = fmaxf(fmaxf(fmaxf(l0, l1), fmaxf(l2, l3)), l4);
    float e0 = expf(l0 - m), e1 = expf(l1 - m), e2 = expf(l2 - m);
    float e3 = expf(l3 - m), e4 = expf(l4 - m);
    float rs = 1.f / (e0 + e1 + e2 + e3 + e4);
    float a0 = e0 * rs, a1 = e1 * rs, a2 = e2 * rs, a3 = e3 * rs, a4 = e4 * rs;

#pragma unroll 8
    for (int d = 0; d < DKK; d++) {
        size_t oq = bq + (size_t)d * TD + t;
        float vc = qkv[oq + VOFF];
        float vm = (t > 0) ? qkv[oq + VOFF - 1] : 0.f;
        float vp = (t < TD - 1) ? qkv[oq + VOFF + 1] : 0.f;
        float att = a0 * vm + a1 * vc + a2 * vp
                  + a3 * keve[bke + KOFF + (size_t)d * TD + t] + a4 * vr[rbase + d];
        sout[base + (size_t)d * TD + t] = xln[base + (size_t)d * TD + t] + att;
    }
}

// ---------------------------------------------------------------------------
// tru attention; ktrvtr: [n][512][T]. grid NTOK (8 heads/block), block 256.
// ---------------------------------------------------------------------------
__global__ void attn_tru(const float* __restrict__ qtr, const float* __restrict__ ktrvtr,
                         const float* __restrict__ ktrr, const float* __restrict__ vtrr,
                         const float* __restrict__ relay, float* __restrict__ z)
{
    __shared__ float sq[8][DKK];
    __shared__ float slog[8][132];
    int wid = threadIdx.x >> 5, lane = threadIdx.x & 31;
    int nh = blockIdx.x * 8 + wid;
    int n = nh >> 3, h = nh & 7;
    int rbase = n * CD + h * DKK;
    size_t bk = ((size_t)n * 512 + h * DKK) * TD;
    const size_t VOFF = (size_t)256 * TD;
    const float sc = 0.17677669529663687f;

    sq[wid][lane] = qtr[rbase + lane];
    __syncwarp();

    float lg[5];
#pragma unroll
    for (int j = 0; j < 5; j++) {
        int l = lane + 32 * j;
        float acc = -1e30f;
        if (l < 129) {
            acc = 0.f;
            if (l == 0) {
#pragma unroll 8
                for (int d = 0; d < DKK; d++) acc += sq[wid][d] * ktrr[rbase + d];
            } else {
                int t = l - 1;
#pragma unroll 8
                for (int d = 0; d < DKK; d++) acc += sq[wid][d] * ktrvtr[bk + (size_t)d * TD + t];
            }
            acc *= sc;
        }
        lg[j] = acc;
    }
    float m = -1e30f;
#pragma unroll
    for (int j = 0; j < 5; j++) m = fmaxf(m, lg[j]);
#pragma unroll
    for (int o = 16; o > 0; o >>= 1) m = fmaxf(m, __shfl_xor_sync(0xffffffffu, m, o));
    float es = 0.f;
#pragma unroll
    for (int j = 0; j < 5; j++) {
        int l = lane + 32 * j;
        if (l < 129) {
            float e = expf(lg[j] - m);
            slog[wid][l] = e;
            es += e;
        }
    }
#pragma unroll
    for (int o = 16; o > 0; o >>= 1) es += __shfl_xor_sync(0xffffffffu, es, o);
    __syncwarp();
    float rinv = 1.f / es;

    int d = lane;
    float att = slog[wid][0] * vtrr[rbase + d];
    const float* vp = ktrvtr + bk + VOFF + (size_t)d * TD;
#pragma unroll 16
    for (int t = 0; t < TD; t++) att += slog[wid][1 + t] * vp[t];
    att *= rinv;
    z[rbase + d] = relay[rbase + d] + att;
}

// ---------------------------------------------------------------------------
// FUSED BatchNorm (stats + affine) over (n,t) per channel. grid 256.
// ---------------------------------------------------------------------------
__global__ void bn_fused_nct(const float* __restrict__ X, const float* __restrict__ g,
                             const float* __restrict__ b, float* __restrict__ Y,
                             uint32_t* __restrict__ Yt, int leaky, float eps)
{
    int c = blockIdx.x, tid = threadIdx.x;
    float s1 = 0.f, s2 = 0.f;
    for (int i = tid; i < NTOK * TD; i += 256) {
        int n = i >> 7, t = i & 127;
        float x = X[((size_t)n * CD + c) * TD + t];
        s1 += x;
        s2 += x * x;
    }
    __shared__ double d1[256], d2[256];
    d1[tid] = s1; d2[tid] = s2;
    __syncthreads();
    for (int s = 128; s > 0; s >>= 1) {
        if (tid < s) { d1[tid] += d1[tid + s]; d2[tid] += d2[tid + s]; }
        __syncthreads();
    }
    __shared__ float smean, sinv;
    if (tid == 0) {
        double mm = d1[0] / (NTOK * TD);
        double var = d2[0] / (NTOK * TD) - mm * mm;
        smean = (float)mm;
        sinv = rsqrtf((float)var + eps);
    }
    __syncthreads();
    float mean = smean, inv = sinv, gg = g[c], bb = b[c];

    for (int i = tid * 4; i < NTOK * TD; i += 1024) {
        int n = i >> 7, t = i & 127;
        size_t off = ((size_t)n * CD + c) * TD + t;
        float4 x4 = *(const float4*)(X + off);
        float v0 = (x4.x - mean) * inv * gg + bb;
        float v1 = (x4.y - mean) * inv * gg + bb;
        float v2 = (x4.z - mean) * inv * gg + bb;
        float v3 = (x4.w - mean) * inv * gg + bb;
        if (leaky) {
            if (v0 < 0.f) v0 *= 0.01f;
            if (v1 < 0.f) v1 *= 0.01f;
            if (v2 < 0.f) v2 *= 0.01f;
            if (v3 < 0.f) v3 *= 0.01f;
        }
        *(float4*)(Y + off) = make_float4(v0, v1, v2, v3);
        if (Yt) {
            uint4 u;
            u.x = f2tf32(v0); u.y = f2tf32(v1);
            u.z = f2tf32(v2); u.w = f2tf32(v3);
            *(uint4*)(Yt + off) = u;
        }
    }
}

// Fused BN over n per channel ([N,C]). grid 256, block 256.
__global__ void bn_fused_nc(const float* __restrict__ X, const float* __restrict__ g,
                            const float* __restrict__ b, float* __restrict__ Y,
                            int leaky, float eps)
{
    int c = blockIdx.x, tid = threadIdx.x;
    float s1 = 0.f, s2 = 0.f;
    for (int n = tid; n < NTOK; n += 256) {
        float x = X[(size_t)n * CD + c];
        s1 += x;
        s2 += x * x;
    }
    __shared__ double d1[256], d2[256];
    d1[tid] = s1; d2[tid] = s2;
    __syncthreads();
    for (int s = 128; s > 0; s >>= 1) {
        if (tid < s) { d1[tid] += d1[tid + s]; d2[tid] += d2[tid + s]; }
        __syncthreads();
    }
    __shared__ float smean, sinv;
    if (tid == 0) {
        double mm = d1[0] / NTOK;
        double var = d2[0] / NTOK - mm * mm;
        smean = (float)mm;
        sinv = rsqrtf((float)var + eps);
    }
    __syncthreads();
    float mean = smean, inv = sinv, gg = g[c], bb = b[c];
    for (int n = tid; n < NTOK; n += 256) {
        float vv = (X[(size_t)n * CD + c] - mean) * inv * gg + bb;
        if (leaky && vv < 0.f) vv *= 0.01f;
        Y[(size_t)n * CD + c] = vv;
    }
}

// ---------------------------------------------------------------------------
extern "C" void kernel_launch(void* const* d_in, const int* in_sizes, int n_in,
                              void* d_out, int out_size)
{
    (void)in_sizes; (void)n_in; (void)out_size;
    const float* data    = (const float*)d_in[0];
    const float* ln_g    = (const float*)d_in[1];
    const float* ln_b    = (const float*)d_in[2];
    const float* tj_wq   = (const float*)d_in[3];
    const float* tj_bq   = (const float*)d_in[4];
    const float* tj_wk   = (const float*)d_in[5];
    const float* tj_bk   = (const float*)d_in[6];
    const float* tj_wv   = (const float*)d_in[7];
    const float* tj_bv   = (const float*)d_in[8];
    const float* tj_bng  = (const float*)d_in[9];
    const float* tj_bnb  = (const float*)d_in[10];
    const float* tj_w1   = (const float*)d_in[11];
    const float* tj_b1   = (const float*)d_in[12];
    const float* tj_w2   = (const float*)d_in[13];
    const float* tj_b2   = (const float*)d_in[14];
    const float* tj_fg   = (const float*)d_in[15];
    const float* tj_fb   = (const float*)d_in[16];
    const float* tr_wq   = (const float*)d_in[17];
    const float* tr_bq   = (const float*)d_in[18];
    const float* tr_wk   = (const float*)d_in[19];
    const float* tr_bk   = (const float*)d_in[20];
    const float* tr_wv   = (const float*)d_in[21];
    const float* tr_bv   = (const float*)d_in[22];
    const float* tr_bng  = (const float*)d_in[23];
    const float* tr_bnb  = (const float*)d_in[24];
    const float* tr_w1   = (const float*)d_in[25];
    const float* tr_b1   = (const float*)d_in[26];
    const float* tr_w2   = (const float*)d_in[27];
    const float* tr_b2   = (const float*)d_in[28];
    const float* tr_fg   = (const float*)d_in[29];
    const float* tr_fb   = (const float*)d_in[30];

    float* buf = nullptr;
    cudaGetSymbolAddress((void**)&buf, g_buf);

    float* embs   = buf + OFF_EMBS;
    float* nodes  = buf + OFF_NODES;
    float* xln    = buf + OFF_XLN;
    float* qkvb   = buf + OFF_QKV;
    float* sb     = buf + OFF_S;
    float* retb   = buf + OFF_RET;
    float* ob     = buf + OFF_O;
    float* ktrvtrb = buf + OFF_KTRVTR;
    uint32_t* hb  = (uint32_t*)(buf + OFF_H);
    float* keveb  = buf + OFF_KEVE;
    float* relayA = buf + OFF_RELAY;
    float* relayB = buf + OFF_RELAYB;
    float* krb    = buf + OFF_KR;
    float* vrb    = buf + OFF_VR;
    float* qtrb   = buf + OFF_QTR;
    float* ktrr   = buf + OFF_KTRR;
    float* vtrr   = buf + OFF_VTRR;
    float* zb     = buf + OFF_Z;
    float* rettb  = buf + OFF_RETT;
    float* otrb   = buf + OFF_OTR;
    float* htrb   = buf + OFF_HTR;

    uint32_t* qkvw  = (uint32_t*)(buf + OFF_QKVW);
    uint32_t* rwkvw = (uint32_t*)(buf + OFF_RWKVW);
    uint32_t* w1_t  = (uint32_t*)(buf + OFF_W1T);
    uint32_t* w2_t  = (uint32_t*)(buf + OFF_W2T);
    uint32_t* xln_t   = (uint32_t*)(buf + OFF_XLN_T);
    uint32_t* embs_t  = (uint32_t*)(buf + OFF_EMBS_T);
    uint32_t* ret_t   = (uint32_t*)(buf + OFF_RET_T);
    uint32_t* nodes_t = (uint32_t*)(buf + OFF_NODES_T);

    cudaFuncSetAttribute(gemm_pre<0,3>, cudaFuncAttributeMaxDynamicSharedMemorySize, GEMM_SMEM);
    cudaFuncSetAttribute(gemm_pre<0,2>, cudaFuncAttributeMaxDynamicSharedMemorySize, GEMM_SMEM);
    cudaFuncSetAttribute(gemm_pre<1,1>, cudaFuncAttributeMaxDynamicSharedMemorySize, GEMM_SMEM);
    cudaFuncSetAttribute(gemm_pre<2,1>, cudaFuncAttributeMaxDynamicSharedMemorySize, GEMM_SMEM);

    // second stream + events (fork/join for graph capture)
    cudaStream_t s2;
    cudaStreamCreateWithFlags(&s2, cudaStreamNonBlocking);
    cudaEvent_t ev_prep, ev_keve, ev_nodes[ITER], ev_relay[ITER];
    cudaEventCreateWithFlags(&ev_prep, cudaEventDisableTiming);
    cudaEventCreateWithFlags(&ev_keve, cudaEventDisableTiming);
    for (int i = 0; i < ITER; i++) {
        cudaEventCreateWithFlags(&ev_nodes[i], cudaEventDisableTiming);
        cudaEventCreateWithFlags(&ev_relay[i], cudaEventDisableTiming);
    }

    // weight conversion (stream1)
    conv_w_frag<<<dim3(CD * CD / 256, ITER), 256>>>(tj_wq, qkvw, CD, CD, LQKV, 0);
    conv_w_frag<<<dim3(CD * CD / 256, ITER), 256>>>(tj_wk, qkvw, CD, CD, LQKV, 2 * SEGQ);
    conv_w_frag<<<dim3(CD * CD / 256, ITER), 256>>>(tj_wv, qkvw, CD, CD, LQKV, 4 * SEGQ);
    conv_w_frag<<<dim3(CD * CD / 256, ITER), 256>>>(tr_wk, rwkvw, CD, CD, LRKV, 0);
    conv_w_frag<<<dim3(CD * CD / 256, ITER), 256>>>(tr_wv, rwkvw, CD, CD, LRKV, 2 * SEGQ);
    conv_w_frag<<<dim3(DFFD * CD / 256, ITER), 256>>>(tj_w1, w1_t, DFFD, CD, LW1, 0);
    conv_w_frag<<<dim3(DFFD * CD / 256, ITER), 256>>>(tj_w2, w2_t, CD, DFFD, LW2, 0);

    prep_kernel<<<dim3(NTOK, 32), dim3(32, 8)>>>(data, embs, embs_t, relayA);
    cudaEventRecord(ev_prep, 0);

    // stream2: all 4 layers' ke/ve from embs
    cudaStreamWaitEvent(s2, ev_prep, 0);
    gemm_pre<0,2><<<dim3(4, NTOK, ITER), 256, GEMM_SMEM, s2>>>(
        qkvw + 2 * SEGQ, tj_bk, tj_bv, nullptr, embs_t, keveb, nullptr,
        512, CD, (size_t)LQKV, (size_t)NTOK * 512 * TD);
    cudaEventRecord(ev_keve, s2);

    for (int i = 0; i < ITER; i++) {
        float* relay_in  = (i & 1) ? relayB : relayA;
        float* relay_out = (i & 1) ? relayA : relayB;
        const float* nodes_in = (i == 0) ? embs : nodes;

        // ---- stream1 main path ----
        ln_kernel<<<dim3(NTOK, 4), dim3(32, 8)>>>(nodes_in, ln_g + i * CD, ln_b + i * CD,
                                                  xln, xln_t);
        gemm_pre<0,3><<<dim3(6, NTOK, 1), 256, GEMM_SMEM>>>(
            qkvw + (size_t)i * LQKV, tj_bq + i * CD, tj_bk + i * CD, tj_bv + i * CD,
            xln_t, qkvb, nullptr, 768, CD, 0, 0);

        if (i > 0) cudaStreamWaitEvent(0, ev_relay[i], 0);   // relay(i) from stream2
        gemm_nc_seg<<<dim3(8, 7), 256>>>(
            tj_wk + (size_t)i * CD * CD, tj_wv + (size_t)i * CD * CD, nullptr,
            tj_bk + i * CD, tj_bv + i * CD, nullptr,
            relay_in, krb, vrb, nullptr, CD);

        if (i == 0) cudaStreamWaitEvent(0, ev_keve, 0);
        attn_tju<<<NTOK * NHH, 128>>>(qkvb, keveb + (size_t)i * NTOK * 512 * TD,
                                      krb, vrb, xln, sb);

        bn_fused_nct<<<256, 256>>>(sb, tj_bng + i * CD, tj_bnb + i * CD,
                                   retb, ret_t, 0, 1e-5f);

        gemm_pre<1,1><<<dim3(8, NTOK, 1), 256, GEMM_SMEM>>>(
            w1_t + (size_t)i * LW1, tj_b1 + i * DFFD, nullptr, nullptr,
            ret_t, (void*)hb, nullptr, DFFD, CD, 0, 0);
        gemm_pre<2,1><<<dim3(2, NTOK, 1), 256, GEMM_SMEM>>>(
            w2_t + (size_t)i * LW2, tj_b2 + i * CD, nullptr, nullptr,
            hb, ob, retb, CD, DFFD, 0, 0);

        float* nodes_out = (i == ITER - 1) ? (float*)d_out : nodes;
        uint32_t* nodes_out_t = (i == ITER - 1) ? nullptr : nodes_t;
        bn_fused_nct<<<256, 256>>>(ob, tj_fg + i * CD, tj_fb + i * CD,
                                   nodes_out, nodes_out_t, 1, 1e-5f);
        cudaEventRecord(ev_nodes[i], 0);

        // ---- stream2 relay path (overlaps next layer's ln+QKV) ----
        if (i < ITER - 1) {
            // qtr/ktrr/vtrr from relay(i): stream2 in-order after its own bnr(i-1)
            gemm_nc_seg<<<dim3(12, 7), 256, 0, s2>>>(
                tr_wq + (size_t)i * CD * CD, tr_wk + (size_t)i * CD * CD,
                tr_wv + (size_t)i * CD * CD,
                tr_bq + i * CD, tr_bk + i * CD, tr_bv + i * CD,
                relay_in, qtrb, ktrr, vtrr, CD);

            cudaStreamWaitEvent(s2, ev_nodes[i], 0);
            gemm_pre<0,2><<<dim3(4, NTOK, 1), 256, GEMM_SMEM, s2>>>(
                rwkvw + (size_t)i * LRKV, tr_bk + i * CD, tr_bv + i * CD, nullptr,
                nodes_t, ktrvtrb, nullptr, 512, CD, 0, 0);

            attn_tru<<<NTOK, 256, 0, s2>>>(qtrb, ktrvtrb, ktrr, vtrr, relay_in, zb);
            bn_fused_nc<<<256, 256, 0, s2>>>(zb, tr_bng + i * CD, tr_bnb + i * CD,
                                             rettb, 0, 1e-5f);
            gemm_nc<1><<<dim3(16, 7), 256, 0, s2>>>(
                tr_w1 + (size_t)i * DFFD * CD, tr_b1 + i * DFFD,
                rettb, htrb, nullptr, DFFD, CD);
            gemm_nc<2><<<dim3(4, 7), 256, 0, s2>>>(
                tr_w2 + (size_t)i * CD * DFFD, tr_b2 + i * CD,
                htrb, otrb, rettb, CD, DFFD);
            bn_fused_nc<<<256, 256, 0, s2>>>(otrb, tr_fg + i * CD, tr_fb + i * CD,
                                             relay_out, 1, 1e-5f);
            cudaEventRecord(ev_relay[i + 1], s2);
        }
    }
}

// round 17
// speedup vs baseline: 1.4259x; 1.4259x over previous
#include <cuda_runtime.h>
#include <math.h>
#include <stdint.h>

#define NTOK 200
#define CD   256
#define TD   128
#define NHH  8
#define DKK  32
#define DFFD 1024
#define ITER 4
#define NCT  (NTOK*CD*TD)
#define NC   (NTOK*CD)

#define OFF_EMBS   0
#define OFF_NODES  (1*NCT)
#define OFF_XLN    (2*NCT)
#define OFF_QKV    (3*NCT)             /* 3 NCT: [n][768][T] */
#define OFF_S      (6*NCT)
#define OFF_RET    (7*NCT)
#define OFF_O      (8*NCT)
#define OFF_KTRVTR (9*NCT)             /* 2 NCT: [n][512][T] */
#define OFF_H      (11*NCT)            /* 4 NCT tf32 */
#define OFF_KEVE   (15*NCT)            /* 8 NCT: 4 layers x [n][512][T] */
#define OFF_RELAY  (23*NCT)
#define OFF_KR     (OFF_RELAY+NC)
#define OFF_VR     (OFF_KR+NC)
#define OFF_QTR    (OFF_VR+NC)
#define OFF_KTRR   (OFF_QTR+NC)
#define OFF_VTRR   (OFF_KTRR+NC)
#define OFF_Z      (OFF_VTRR+NC)
#define OFF_RETT   (OFF_Z+NC)
#define OFF_OTR    (OFF_RETT+NC)
#define OFF_HTR    (OFF_OTR+NC)
#define OFF_MEAN   (OFF_HTR+NTOK*DFFD)
#define OFF_INV    (OFF_MEAN+256)

/* fragment-major tf32 weights */
#define SEGQ       (128*256)
#define LQKV       (6*SEGQ)
#define LRKV       (4*SEGQ)
#define LW1        (DFFD*CD)
#define LW2        (CD*DFFD)
#define OFF_QKVW   (OFF_INV+256)
#define OFF_RWKVW  (OFF_QKVW + LQKV*ITER)
#define OFF_W1T    (OFF_RWKVW + LRKV*ITER)
#define OFF_W2T    (OFF_W1T + LW1*ITER)
#define OFF_XLN_T  (OFF_W2T + LW2*ITER)
#define OFF_EMBS_T (OFF_XLN_T + NCT)
#define OFF_RET_T  (OFF_EMBS_T + NCT)
#define OFF_NODES_T (OFF_RET_T + NCT)
#define BUF_TOTAL  (OFF_NODES_T + NCT)

__device__ __align__(16) float g_buf[BUF_TOTAL];

__device__ __forceinline__ uint32_t f2tf32(float x) {
    uint32_t r;
    asm("cvt.rna.tf32.f32 %0, %1;" : "=r"(r) : "f"(x));
    return r;
}

#define MMA_TF32(C, A, B)                                                     \
    asm volatile("mma.sync.aligned.m16n8k8.row.col.f32.tf32.tf32.f32 "        \
                 "{%0,%1,%2,%3}, {%4,%5,%6,%7}, {%8,%9}, {%0,%1,%2,%3};\n"    \
                 : "+f"((C)[0]), "+f"((C)[1]), "+f"((C)[2]), "+f"((C)[3])     \
                 : "r"((A)[0]), "r"((A)[1]), "r"((A)[2]), "r"((A)[3]),        \
                   "r"((B)[0]), "r"((B)[1]));

#define CP16(daddr, src)                                                      \
    asm volatile("cp.async.cg.shared.global [%0], [%1], 16;"                  \
                 :: "r"(daddr), "l"(src))
#define CP_COMMIT asm volatile("cp.async.commit_group;")
#define CP_WAIT(N) asm volatile("cp.async.wait_group %0;" :: "n"(N))

// ---------------------------------------------------------------------------
// Convert W (fp32 [layer][O][Cin]) to fragment-major tf32 at dst offset.
// ---------------------------------------------------------------------------
__global__ void conv_w_frag(const float* __restrict__ W, uint32_t* __restrict__ Wt,
                            int O, int Cin, size_t dl, size_t doff)
{
    size_t sbase = (size_t)blockIdx.y * O * Cin;
    size_t dbase = (size_t)blockIdx.y * dl + doff;
    int idx = blockIdx.x * 256 + threadIdx.x;
    if (idx >= O * Cin) return;
    int NCH = Cin >> 5;
    int j = idx & 3, sl = (idx >> 2) & 31, f = (idx >> 7) & 31;
    int rest = idx >> 12;
    int c = rest % NCH, ob = rest / NCH;
    int r = ob * 128 + (f >> 2) * 16 + (sl >> 2) + ((j & 1) << 3);
    int col = c * 32 + (f & 3) * 8 + (sl & 3) + ((j >> 1) << 2);
    Wt[dbase + idx] = f2tf32(W[sbase + (size_t)r * Cin + col]);
}

// ---------------------------------------------------------------------------
// prep
// ---------------------------------------------------------------------------
__global__ void prep_kernel(const float* __restrict__ data,
                            float* __restrict__ embs, uint32_t* __restrict__ embs_t,
                            float* __restrict__ relay)
{
    int n = blockIdx.x;
    int b = n / 25, v = n % 25;
    int c = blockIdx.y * 8 + threadIdx.y;
    int tx = threadIdx.x;
    const float* src = data + (((size_t)b * CD + c) * 25 + v) * TD;
    size_t dof = ((size_t)n * CD + c) * TD;
    float s = 0.f;
#pragma unroll
    for (int j = 0; j < 4; j++) {
        int t = tx + 32 * j;
        float x = src[t];
        embs[dof + t] = x;
        embs_t[dof + t] = f2tf32(x);
        s += x;
    }
#pragma unroll
    for (int o = 16; o > 0; o >>= 1) s += __shfl_xor_sync(0xffffffffu, s, o);
    if (tx == 0) relay[n * CD + c] = s * (1.0f / 128.0f);
}

// ---------------------------------------------------------------------------
// LayerNorm; writes fp32 + tf32. grid (NTOK,4), block (32,8)
// ---------------------------------------------------------------------------
__global__ void ln_kernel(const float* __restrict__ X, const float* __restrict__ g,
                          const float* __restrict__ b, float* __restrict__ Y,
                          uint32_t* __restrict__ Yt)
{
    int n = blockIdx.x;
    int t = blockIdx.y * 32 + threadIdx.x;
    int tx = threadIdx.x, ty = threadIdx.y;
    float x[32];
    float s1 = 0.f, s2 = 0.f;
#pragma unroll
    for (int j = 0; j < 32; j++) {
        int c = ty + j * 8;
        x[j] = X[((size_t)n * CD + c) * TD + t];
        s1 += x[j];
        s2 += x[j] * x[j];
    }
    __shared__ float sm1[8][32], sm2[8][32], smean[32], sinv[32];
    sm1[ty][tx] = s1; sm2[ty][tx] = s2;
    __syncthreads();
    if (ty == 0) {
        float a = 0.f, bb = 0.f;
#pragma unroll
        for (int qy = 0; qy < 8; qy++) { a += sm1[qy][tx]; bb += sm2[qy][tx]; }
        float m = a * (1.0f / 256.0f);
        float var = bb * (1.0f / 256.0f) - m * m;
        smean[tx] = m;
        sinv[tx] = rsqrtf(var + 1e-6f);
    }
    __syncthreads();
    float m = smean[tx], inv = sinv[tx];
#pragma unroll
    for (int j = 0; j < 32; j++) {
        int c = ty + j * 8;
        float vv = (x[j] - m) * inv * g[c] + b[c];
        size_t off = ((size_t)n * CD + c) * TD + t;
        Y[off] = vv;
        Yt[off] = f2tf32(vv);
    }
}

// ---------------------------------------------------------------------------
// TF32 GEMM, pre-converted operands + cp.async 3-stage pipeline.
// ---------------------------------------------------------------------------
#define XS_STR   132
#define WF_U32   (32 * 128)
#define BUFU     (WF_U32 + 32 * XS_STR)
#define GEMM_SMEM (3 * BUFU * 4)

template <int EPI, int NSEG>
__global__ __launch_bounds__(256, 2)
void gemm_pre(const uint32_t* __restrict__ Wt, const float* __restrict__ b0,
              const float* __restrict__ b1, const float* __restrict__ b2,
              const uint32_t* __restrict__ Xt, void* __restrict__ Yout,
              const float* __restrict__ Res, int O, int Cin,
              size_t wl, size_t yl)
{
    extern __shared__ __align__(16) uint32_t smem_dyn[];
    uint32_t smem_base = (uint32_t)__cvta_generic_to_shared(smem_dyn);

    int n = blockIdx.y;
    int z = blockIdx.z;
    int nchunks = Cin >> 5;
    const uint32_t* Wblk = Wt + (size_t)z * wl + (size_t)blockIdx.x * nchunks * WF_U32;
    const uint32_t* Xn = Xt + (size_t)n * Cin * TD;
    int tid = threadIdx.x;
    int lane = tid & 31, wid = tid >> 5;
    int warp_o = wid >> 2, warp_t = wid & 3;
    int g = lane >> 2, q = lane & 3;

#define ISSUE(c)                                                              \
    do {                                                                      \
        int bsel = (c) % 3;                                                   \
        uint32_t wb = smem_base + bsel * (BUFU * 4);                          \
        uint32_t xb = wb + WF_U32 * 4;                                        \
        const uint32_t* wsrc = Wblk + (size_t)(c) * WF_U32;                   \
        const uint32_t* xsrc = Xn + (size_t)(c) * 32 * TD;                    \
        _Pragma("unroll")                                                     \
        for (int r = 0; r < 4; r++) {                                         \
            int i = tid + 256 * r;                                            \
            CP16(wb + (uint32_t)i * 16, wsrc + i * 4);                        \
            int k = i >> 5, c4 = i & 31;                                      \
            CP16(xb + (uint32_t)(k * XS_STR + c4 * 4) * 4,                    \
                 xsrc + (size_t)k * TD + c4 * 4);                             \
        }                                                                     \
        CP_COMMIT;                                                            \
    } while (0)

    ISSUE(0);
    if (nchunks > 1) ISSUE(1);

    float acc[4][4][4];
#pragma unroll
    for (int m = 0; m < 4; m++)
#pragma unroll
        for (int nf = 0; nf < 4; nf++)
#pragma unroll
            for (int j = 0; j < 4; j++) acc[m][nf][j] = 0.f;

    int cidx = warp_t * 32 + g;
    for (int c = 0; c < nchunks; c++) {
        if (c + 1 < nchunks) { CP_WAIT(1); } else { CP_WAIT(0); }
        __syncthreads();
        if (c + 2 < nchunks) ISSUE(c + 2);

        const uint32_t* Wb = smem_dyn + (c % 3) * BUFU;
        const uint32_t* Xb = Wb + WF_U32;
#pragma unroll
        for (int kt = 0; kt < 4; kt++) {
            uint32_t a[4][4], b[4][2];
#pragma unroll
            for (int m = 0; m < 4; m++) {
                int f = (warp_o * 4 + m) * 4 + kt;
                *(uint4*)a[m] = *(const uint4*)&Wb[f * 128 + lane * 4];
            }
            const uint32_t* xrow0 = &Xb[(kt * 8 + q) * XS_STR + cidx];
            const uint32_t* xrow1 = xrow0 + 4 * XS_STR;
#pragma unroll
            for (int nf = 0; nf < 4; nf++) {
                b[nf][0] = xrow0[nf * 8];
                b[nf][1] = xrow1[nf * 8];
            }
#pragma unroll
            for (int m = 0; m < 4; m++)
#pragma unroll
                for (int nf = 0; nf < 4; nf++)
                    MMA_TF32(acc[m][nf], a[m], b[nf]);
        }
    }
#undef ISSUE

#pragma unroll
    for (int m = 0; m < 4; m++) {
        int obase = blockIdx.x * 128 + warp_o * 64 + m * 16 + g;
#pragma unroll
        for (int r = 0; r < 2; r++) {
            int o = obase + r * 8;
            float bs;
            if (NSEG == 1) {
                bs = b0[o];
            } else {
                int seg = o >> 8;
                const float* bp = (seg == 0) ? b0 : (seg == 1 ? b1 : b2);
                bs = bp[z * 256 + (o & 255)];
            }
            size_t rowoff = (size_t)z * yl + ((size_t)n * O + o) * TD;
#pragma unroll
            for (int nf = 0; nf < 4; nf++) {
                int t = warp_t * 32 + nf * 8 + q * 2;
                float v0 = acc[m][nf][r * 2 + 0] + bs;
                float v1 = acc[m][nf][r * 2 + 1] + bs;
                if (EPI == 1) {
                    v0 = fmaxf(v0, 0.f); v1 = fmaxf(v1, 0.f);
                    uint2 uu;
                    uu.x = f2tf32(v0); uu.y = f2tf32(v1);
                    *(uint2*)((uint32_t*)Yout + rowoff + t) = uu;
                } else {
                    if (EPI == 2) {
                        float2 rr = *(const float2*)(Res + rowoff + t);
                        v0 += rr.x; v1 += rr.y;
                    }
                    *(float2*)((float*)Yout + rowoff + t) = make_float2(v0, v1);
                }
            }
        }
    }
}

// ---------------------------------------------------------------------------
// Small GEMM over [N, Cin] tokens (relay path, fp32). Single weight/out.
// ---------------------------------------------------------------------------
template <int EPI>
__global__ __launch_bounds__(256)
void gemm_nc(const float* __restrict__ W, const float* __restrict__ bias,
             const float* __restrict__ X, float* __restrict__ Y,
             const float* __restrict__ Res, int O, int Cin)
{
    int o0 = blockIdx.x * 64;
    int n0 = blockIdx.y * 32;
    int tid = threadIdx.x;
    int tx = tid & 31, ty = tid >> 5;

    __shared__ float Ws[32][64];
    __shared__ float Xs[32][33];

    float acc[8];
#pragma unroll
    for (int i = 0; i < 8; i++) acc[i] = 0.f;

    for (int k0 = 0; k0 < Cin; k0 += 32) {
#pragma unroll
        for (int r = 0; r < 2; r++) {
            int idx = tid + 256 * r;
            int o = idx >> 3, kq = idx & 7;
            float4 w4 = *(const float4*)(W + (size_t)(o0 + o) * Cin + k0 + kq * 4);
            Ws[kq * 4 + 0][o] = w4.x;
            Ws[kq * 4 + 1][o] = w4.y;
            Ws[kq * 4 + 2][o] = w4.z;
            Ws[kq * 4 + 3][o] = w4.w;
        }
        {
            int nn = tid >> 3, kq = tid & 7;
            int n = n0 + nn;
            float4 x4 = make_float4(0.f, 0.f, 0.f, 0.f);
            if (n < NTOK) x4 = *(const float4*)(X + (size_t)n * Cin + k0 + kq * 4);
            Xs[kq * 4 + 0][nn] = x4.x;
            Xs[kq * 4 + 1][nn] = x4.y;
            Xs[kq * 4 + 2][nn] = x4.z;
            Xs[kq * 4 + 3][nn] = x4.w;
        }
        __syncthreads();
#pragma unroll
        for (int kk = 0; kk < 32; kk++) {
            float bv = Xs[kk][tx];
#pragma unroll
            for (int i = 0; i < 8; i++) acc[i] += Ws[kk][ty * 8 + i] * bv;
        }
        __syncthreads();
    }

    int n = n0 + tx;
    if (n < NTOK) {
#pragma unroll
        for (int i = 0; i < 8; i++) {
            int o = o0 + ty * 8 + i;
            float val = acc[i] + bias[o];
            if (EPI == 1) val = fmaxf(val, 0.f);
            if (EPI == 2) val += Res[(size_t)n * O + o];
            Y[(size_t)n * O + o] = val;
        }
    }
}

// ---------------------------------------------------------------------------
// Segmented small GEMM: up to 3 weight sets of [256][Cin] with own bias/out.
// grid (nseg*4, 7). Per-64-o block arithmetic identical to gemm_nc.
// ---------------------------------------------------------------------------
__global__ __launch_bounds__(256)
void gemm_nc_seg(const float* __restrict__ w0, const float* __restrict__ w1,
                 const float* __restrict__ w2,
                 const float* __restrict__ b0, const float* __restrict__ b1,
                 const float* __restrict__ b2,
                 const float* __restrict__ X,
                 float* __restrict__ y0, float* __restrict__ y1,
                 float* __restrict__ y2, int Cin)
{
    int o0g = blockIdx.x * 64;
    int seg = o0g >> 8;
    const float* W = (seg == 0) ? w0 : (seg == 1 ? w1 : w2);
    const float* bias = (seg == 0) ? b0 : (seg == 1 ? b1 : b2);
    float* Y = (seg == 0) ? y0 : (seg == 1 ? y1 : y2);
    int o0 = o0g & 255;
    int n0 = blockIdx.y * 32;
    int tid = threadIdx.x;
    int tx = tid & 31, ty = tid >> 5;

    __shared__ float Ws[32][64];
    __shared__ float Xs[32][33];

    float acc[8];
#pragma unroll
    for (int i = 0; i < 8; i++) acc[i] = 0.f;

    for (int k0 = 0; k0 < Cin; k0 += 32) {
#pragma unroll
        for (int r = 0; r < 2; r++) {
            int idx = tid + 256 * r;
            int o = idx >> 3, kq = idx & 7;
            float4 w4 = *(const float4*)(W + (size_t)(o0 + o) * Cin + k0 + kq * 4);
            Ws[kq * 4 + 0][o] = w4.x;
            Ws[kq * 4 + 1][o] = w4.y;
            Ws[kq * 4 + 2][o] = w4.z;
            Ws[kq * 4 + 3][o] = w4.w;
        }
        {
            int nn = tid >> 3, kq = tid & 7;
            int n = n0 + nn;
            float4 x4 = make_float4(0.f, 0.f, 0.f, 0.f);
            if (n < NTOK) x4 = *(const float4*)(X + (size_t)n * Cin + k0 + kq * 4);
            Xs[kq * 4 + 0][nn] = x4.x;
            Xs[kq * 4 + 1][nn] = x4.y;
            Xs[kq * 4 + 2][nn] = x4.z;
            Xs[kq * 4 + 3][nn] = x4.w;
        }
        __syncthreads();
#pragma unroll
        for (int kk = 0; kk < 32; kk++) {
            float bv = Xs[kk][tx];
#pragma unroll
            for (int i = 0; i < 8; i++) acc[i] += Ws[kk][ty * 8 + i] * bv;
        }
        __syncthreads();
    }

    int n = n0 + tx;
    if (n < NTOK) {
#pragma unroll
        for (int i = 0; i < 8; i++) {
            int o = o0 + ty * 8 + i;
            Y[(size_t)n * 256 + o] = acc[i] + bias[o];
        }
    }
}

// ---------------------------------------------------------------------------
// tju attention. qkv: [n][768][T]; keve: [n][512][T]. grid NTOK*NHH, block 128.
// Neighbor k/v values fetched via warp shuffle (bit-identical values; memory
// load only at warp-boundary lanes).
// ---------------------------------------------------------------------------
__global__ void attn_tju(const float* __restrict__ qkv, const float* __restrict__ keve,
                         const float* __restrict__ kr, const float* __restrict__ vr,
                         const float* __restrict__ xln, float* __restrict__ sout)
{
    int nh = blockIdx.x;
    int n = nh >> 3, h = nh & 7;
    int t = threadIdx.x;
    int lane = t & 31;
    int rbase = n * CD + h * DKK;
    size_t base = (size_t)rbase * TD;
    size_t bq = ((size_t)n * 768 + h * DKK) * TD;
    size_t bke = ((size_t)n * 512 + h * DKK) * TD;
    const size_t KOFF = (size_t)256 * TD, VOFF = (size_t)512 * TD;

    float l0 = 0.f, l1 = 0.f, l2 = 0.f, l3 = 0.f, l4 = 0.f;
#pragma unroll 8
    for (int d = 0; d < DKK; d++) {
        size_t oq = bq + (size_t)d * TD + t;
        float qd = qkv[oq];
        float kc = qkv[oq + KOFF];
        float km = __shfl_up_sync(0xffffffffu, kc, 1);
        if (lane == 0) km = (t > 0) ? qkv[oq + KOFF - 1] : 0.f;
        float kp = __shfl_down_sync(0xffffffffu, kc, 1);
        if (lane == 31) kp = (t < TD - 1) ? qkv[oq + KOFF + 1] : 0.f;
        l0 += qd * km;
        l1 += qd * kc;
        l2 += qd * kp;
        l3 += qd * keve[bke + (size_t)d * TD + t];
        l4 += qd * kr[rbase + d];
    }
    const float sc = 0.17677669529663687f;
    l0 *= sc; l1 *= sc; l2 *= sc; l3 *= sc; l4 *= sc;
    float m = fmaxf(fmaxf(fmaxf(l0, l1), fmaxf(l2, l3)), l4);
    float e0 = expf(l0 - m), e1 = expf(l1 - m), e2 = expf(l2 - m);
    float e3 = expf(l3 - m), e4 = expf(l4 - m);
    float rs = 1.f / (e0 + e1 + e2 + e3 + e4);
    float a0 = e0 * rs, a1 = e1 * rs, a2 = e2 * rs, a3 = e3 * rs, a4 = e4 * rs;

#pragma unroll 8
    for (int d = 0; d < DKK; d++) {
        size_t oq = bq + (size_t)d * TD + t;
        float vc = qkv[oq + VOFF];
        float vm = __shfl_up_sync(0xffffffffu, vc, 1);
        if (lane == 0) vm = (t > 0) ? qkv[oq + VOFF - 1] : 0.f;
        float vp = __shfl_down_sync(0xffffffffu, vc, 1);
        if (lane == 31) vp = (t < TD - 1) ? qkv[oq + VOFF + 1] : 0.f;
        float att = a0 * vm + a1 * vc + a2 * vp
                  + a3 * keve[bke + KOFF + (size_t)d * TD + t] + a4 * vr[rbase + d];
        sout[base + (size_t)d * TD + t] = xln[base + (size_t)d * TD + t] + att;
    }
}

// ---------------------------------------------------------------------------
// tru attention; ktrvtr: [n][512][T]. grid NTOK (8 heads/block), block 256.
// ---------------------------------------------------------------------------
__global__ void attn_tru(const float* __restrict__ qtr, const float* __restrict__ ktrvtr,
                         const float* __restrict__ ktrr, const float* __restrict__ vtrr,
                         const float* __restrict__ relay, float* __restrict__ z)
{
    __shared__ float sq[8][DKK];
    __shared__ float slog[8][132];
    int wid = threadIdx.x >> 5, lane = threadIdx.x & 31;
    int nh = blockIdx.x * 8 + wid;
    int n = nh >> 3, h = nh & 7;
    int rbase = n * CD + h * DKK;
    size_t bk = ((size_t)n * 512 + h * DKK) * TD;
    const size_t VOFF = (size_t)256 * TD;
    const float sc = 0.17677669529663687f;

    sq[wid][lane] = qtr[rbase + lane];
    __syncwarp();

    float lg[5];
#pragma unroll
    for (int j = 0; j < 5; j++) {
        int l = lane + 32 * j;
        float acc = -1e30f;
        if (l < 129) {
            acc = 0.f;
            if (l == 0) {
#pragma unroll 8
                for (int d = 0; d < DKK; d++) acc += sq[wid][d] * ktrr[rbase + d];
            } else {
                int t = l - 1;
#pragma unroll 8
                for (int d = 0; d < DKK; d++) acc += sq[wid][d] * ktrvtr[bk + (size_t)d * TD + t];
            }
            acc *= sc;
        }
        lg[j] = acc;
    }
    float m = -1e30f;
#pragma unroll
    for (int j = 0; j < 5; j++) m = fmaxf(m, lg[j]);
#pragma unroll
    for (int o = 16; o > 0; o >>= 1) m = fmaxf(m, __shfl_xor_sync(0xffffffffu, m, o));
    float es = 0.f;
#pragma unroll
    for (int j = 0; j < 5; j++) {
        int l = lane + 32 * j;
        if (l < 129) {
            float e = expf(lg[j] - m);
            slog[wid][l] = e;
            es += e;
        }
    }
#pragma unroll
    for (int o = 16; o > 0; o >>= 1) es += __shfl_xor_sync(0xffffffffu, es, o);
    __syncwarp();
    float rinv = 1.f / es;

    int d = lane;
    float att = slog[wid][0] * vtrr[rbase + d];
    const float* vp = ktrvtr + bk + VOFF + (size_t)d * TD;
#pragma unroll 16
    for (int t = 0; t < TD; t++) att += slog[wid][1 + t] * vp[t];
    att *= rinv;
    z[rbase + d] = relay[rbase + d] + att;
}

// ---------------------------------------------------------------------------
// FUSED BatchNorm (stats + affine) over (n,t) per channel. grid 256.
// Stats loop vectorized float4 (same set of addends; partial-sum partition
// changes -> mean/inv differ only in last bits).
// ---------------------------------------------------------------------------
__global__ void bn_fused_nct(const float* __restrict__ X, const float* __restrict__ g,
                             const float* __restrict__ b, float* __restrict__ Y,
                             uint32_t* __restrict__ Yt, int leaky, float eps)
{
    int c = blockIdx.x, tid = threadIdx.x;
    float s1 = 0.f, s2 = 0.f;
    for (int i = tid * 4; i < NTOK * TD; i += 1024) {
        int n = i >> 7, t = i & 127;
        float4 x4 = *(const float4*)(X + ((size_t)n * CD + c) * TD + t);
        s1 += x4.x + x4.y + x4.z + x4.w;
        s2 += x4.x * x4.x + x4.y * x4.y + x4.z * x4.z + x4.w * x4.w;
    }
    __shared__ double d1[256], d2[256];
    d1[tid] = s1; d2[tid] = s2;
    __syncthreads();
    for (int s = 128; s > 0; s >>= 1) {
        if (tid < s) { d1[tid] += d1[tid + s]; d2[tid] += d2[tid + s]; }
        __syncthreads();
    }
    __shared__ float smean, sinv;
    if (tid == 0) {
        double mm = d1[0] / (NTOK * TD);
        double var = d2[0] / (NTOK * TD) - mm * mm;
        smean = (float)mm;
        sinv = rsqrtf((float)var + eps);
    }
    __syncthreads();
    float mean = smean, inv = sinv, gg = g[c], bb = b[c];

    for (int i = tid * 4; i < NTOK * TD; i += 1024) {
        int n = i >> 7, t = i & 127;
        size_t off = ((size_t)n * CD + c) * TD + t;
        float4 x4 = *(const float4*)(X + off);
        float v0 = (x4.x - mean) * inv * gg + bb;
        float v1 = (x4.y - mean) * inv * gg + bb;
        float v2 = (x4.z - mean) * inv * gg + bb;
        float v3 = (x4.w - mean) * inv * gg + bb;
        if (leaky) {
            if (v0 < 0.f) v0 *= 0.01f;
            if (v1 < 0.f) v1 *= 0.01f;
            if (v2 < 0.f) v2 *= 0.01f;
            if (v3 < 0.f) v3 *= 0.01f;
        }
        *(float4*)(Y + off) = make_float4(v0, v1, v2, v3);
        if (Yt) {
            uint4 u;
            u.x = f2tf32(v0); u.y = f2tf32(v1);
            u.z = f2tf32(v2); u.w = f2tf32(v3);
            *(uint4*)(Yt + off) = u;
        }
    }
}

// Fused BN over n per channel ([N,C]). grid 256, block 256.
__global__ void bn_fused_nc(const float* __restrict__ X, const float* __restrict__ g,
                            const float* __restrict__ b, float* __restrict__ Y,
                            int leaky, float eps)
{
    int c = blockIdx.x, tid = threadIdx.x;
    float s1 = 0.f, s2 = 0.f;
    for (int n = tid; n < NTOK; n += 256) {
        float x = X[(size_t)n * CD + c];
        s1 += x;
        s2 += x * x;
    }
    __shared__ double d1[256], d2[256];
    d1[tid] = s1; d2[tid] = s2;
    __syncthreads();
    for (int s = 128; s > 0; s >>= 1) {
        if (tid < s) { d1[tid] += d1[tid + s]; d2[tid] += d2[tid + s]; }
        __syncthreads();
    }
    __shared__ float smean, sinv;
    if (tid == 0) {
        double mm = d1[0] / NTOK;
        double var = d2[0] / NTOK - mm * mm;
        smean = (float)mm;
        sinv = rsqrtf((float)var + eps);
    }
    __syncthreads();
    float mean = smean, inv = sinv, gg = g[c], bb = b[c];
    for (int n = tid; n < NTOK; n += 256) {
        float vv = (X[(size_t)n * CD + c] - mean) * inv * gg + bb;
        if (leaky && vv < 0.f) vv *= 0.01f;
        Y[(size_t)n * CD + c] = vv;
    }
}

// ---------------------------------------------------------------------------
extern "C" void kernel_launch(void* const* d_in, const int* in_sizes, int n_in,
                              void* d_out, int out_size)
{
    (void)in_sizes; (void)n_in; (void)out_size;
    const float* data    = (const float*)d_in[0];
    const float* ln_g    = (const float*)d_in[1];
    const float* ln_b    = (const float*)d_in[2];
    const float* tj_wq   = (const float*)d_in[3];
    const float* tj_bq   = (const float*)d_in[4];
    const float* tj_wk   = (const float*)d_in[5];
    const float* tj_bk   = (const float*)d_in[6];
    const float* tj_wv   = (const float*)d_in[7];
    const float* tj_bv   = (const float*)d_in[8];
    const float* tj_bng  = (const float*)d_in[9];
    const float* tj_bnb  = (const float*)d_in[10];
    const float* tj_w1   = (const float*)d_in[11];
    const float* tj_b1   = (const float*)d_in[12];
    const float* tj_w2   = (const float*)d_in[13];
    const float* tj_b2   = (const float*)d_in[14];
    const float* tj_fg   = (const float*)d_in[15];
    const float* tj_fb   = (const float*)d_in[16];
    const float* tr_wq   = (const float*)d_in[17];
    const float* tr_bq   = (const float*)d_in[18];
    const float* tr_wk   = (const float*)d_in[19];
    const float* tr_bk   = (const float*)d_in[20];
    const float* tr_wv   = (const float*)d_in[21];
    const float* tr_bv   = (const float*)d_in[22];
    const float* tr_bng  = (const float*)d_in[23];
    const float* tr_bnb  = (const float*)d_in[24];
    const float* tr_w1   = (const float*)d_in[25];
    const float* tr_b1   = (const float*)d_in[26];
    const float* tr_w2   = (const float*)d_in[27];
    const float* tr_b2   = (const float*)d_in[28];
    const float* tr_fg   = (const float*)d_in[29];
    const float* tr_fb   = (const float*)d_in[30];

    float* buf = nullptr;
    cudaGetSymbolAddress((void**)&buf, g_buf);

    float* embs   = buf + OFF_EMBS;
    float* nodes  = buf + OFF_NODES;
    float* xln    = buf + OFF_XLN;
    float* qkvb   = buf + OFF_QKV;
    float* sb     = buf + OFF_S;
    float* retb   = buf + OFF_RET;
    float* ob     = buf + OFF_O;
    float* ktrvtrb = buf + OFF_KTRVTR;
    uint32_t* hb  = (uint32_t*)(buf + OFF_H);
    float* keveb  = buf + OFF_KEVE;
    float* relay  = buf + OFF_RELAY;
    float* krb    = buf + OFF_KR;
    float* vrb    = buf + OFF_VR;
    float* qtrb   = buf + OFF_QTR;
    float* ktrr   = buf + OFF_KTRR;
    float* vtrr   = buf + OFF_VTRR;
    float* zb     = buf + OFF_Z;
    float* rettb  = buf + OFF_RETT;
    float* otrb   = buf + OFF_OTR;
    float* htrb   = buf + OFF_HTR;

    uint32_t* qkvw  = (uint32_t*)(buf + OFF_QKVW);
    uint32_t* rwkvw = (uint32_t*)(buf + OFF_RWKVW);
    uint32_t* w1_t  = (uint32_t*)(buf + OFF_W1T);
    uint32_t* w2_t  = (uint32_t*)(buf + OFF_W2T);
    uint32_t* xln_t   = (uint32_t*)(buf + OFF_XLN_T);
    uint32_t* embs_t  = (uint32_t*)(buf + OFF_EMBS_T);
    uint32_t* ret_t   = (uint32_t*)(buf + OFF_RET_T);
    uint32_t* nodes_t = (uint32_t*)(buf + OFF_NODES_T);

    cudaFuncSetAttribute(gemm_pre<0,3>, cudaFuncAttributeMaxDynamicSharedMemorySize, GEMM_SMEM);
    cudaFuncSetAttribute(gemm_pre<0,2>, cudaFuncAttributeMaxDynamicSharedMemorySize, GEMM_SMEM);
    cudaFuncSetAttribute(gemm_pre<1,1>, cudaFuncAttributeMaxDynamicSharedMemorySize, GEMM_SMEM);
    cudaFuncSetAttribute(gemm_pre<2,1>, cudaFuncAttributeMaxDynamicSharedMemorySize, GEMM_SMEM);

    // weight conversion into combined fragment-major layouts
    conv_w_frag<<<dim3(CD * CD / 256, ITER), 256>>>(tj_wq, qkvw, CD, CD, LQKV, 0);
    conv_w_frag<<<dim3(CD * CD / 256, ITER), 256>>>(tj_wk, qkvw, CD, CD, LQKV, 2 * SEGQ);
    conv_w_frag<<<dim3(CD * CD / 256, ITER), 256>>>(tj_wv, qkvw, CD, CD, LQKV, 4 * SEGQ);
    conv_w_frag<<<dim3(CD * CD / 256, ITER), 256>>>(tr_wk, rwkvw, CD, CD, LRKV, 0);
    conv_w_frag<<<dim3(CD * CD / 256, ITER), 256>>>(tr_wv, rwkvw, CD, CD, LRKV, 2 * SEGQ);
    conv_w_frag<<<dim3(DFFD * CD / 256, ITER), 256>>>(tj_w1, w1_t, DFFD, CD, LW1, 0);
    conv_w_frag<<<dim3(DFFD * CD / 256, ITER), 256>>>(tj_w2, w2_t, CD, DFFD, LW2, 0);

    prep_kernel<<<dim3(NTOK, 32), dim3(32, 8)>>>(data, embs, embs_t, relay);

    // all 4 layers' ke/ve from embs (layer-batched)
    gemm_pre<0,2><<<dim3(4, NTOK, ITER), 256, GEMM_SMEM>>>(
        qkvw + 2 * SEGQ, tj_bk, tj_bv, nullptr, embs_t, keveb, nullptr,
        512, CD, (size_t)LQKV, (size_t)NTOK * 512 * TD);

    for (int i = 0; i < ITER; i++) {
        const float* nodes_in = (i == 0) ? embs : nodes;
        ln_kernel<<<dim3(NTOK, 4), dim3(32, 8)>>>(nodes_in, ln_g + i * CD, ln_b + i * CD,
                                                  xln, xln_t);

        // fused QKV (O=768)
        gemm_pre<0,3><<<dim3(6, NTOK, 1), 256, GEMM_SMEM>>>(
            qkvw + (size_t)i * LQKV, tj_bq + i * CD, tj_bk + i * CD, tj_bv + i * CD,
            xln_t, qkvb, nullptr, 768, CD, 0, 0);
        // kr + vr in one segmented launch
        gemm_nc_seg<<<dim3(8, 7), 256>>>(
            tj_wk + (size_t)i * CD * CD, tj_wv + (size_t)i * CD * CD, nullptr,
            tj_bk + i * CD, tj_bv + i * CD, nullptr,
            relay, krb, vrb, nullptr, CD);

        attn_tju<<<NTOK * NHH, 128>>>(qkvb, keveb + (size_t)i * NTOK * 512 * TD,
                                      krb, vrb, xln, sb);

        bn_fused_nct<<<256, 256>>>(sb, tj_bng + i * CD, tj_bnb + i * CD,
                                   retb, ret_t, 0, 1e-5f);

        gemm_pre<1,1><<<dim3(8, NTOK, 1), 256, GEMM_SMEM>>>(
            w1_t + (size_t)i * LW1, tj_b1 + i * DFFD, nullptr, nullptr,
            ret_t, (void*)hb, nullptr, DFFD, CD, 0, 0);
        gemm_pre<2,1><<<dim3(2, NTOK, 1), 256, GEMM_SMEM>>>(
            w2_t + (size_t)i * LW2, tj_b2 + i * CD, nullptr, nullptr,
            hb, ob, retb, CD, DFFD, 0, 0);

        float* nodes_out = (i == ITER - 1) ? (float*)d_out : nodes;
        uint32_t* nodes_out_t = (i == ITER - 1) ? nullptr : nodes_t;
        bn_fused_nct<<<256, 256>>>(ob, tj_fg + i * CD, tj_fb + i * CD,
                                   nodes_out, nodes_out_t, 1, 1e-5f);

        if (i < ITER - 1) {
            // qtr + ktrr + vtrr in one segmented launch
            gemm_nc_seg<<<dim3(12, 7), 256>>>(
                tr_wq + (size_t)i * CD * CD, tr_wk + (size_t)i * CD * CD,
                tr_wv + (size_t)i * CD * CD,
                tr_bq + i * CD, tr_bk + i * CD, tr_bv + i * CD,
                relay, qtrb, ktrr, vtrr, CD);
            // fused ktr/vtr (O=512)
            gemm_pre<0,2><<<dim3(4, NTOK, 1), 256, GEMM_SMEM>>>(
                rwkvw + (size_t)i * LRKV, tr_bk + i * CD, tr_bv + i * CD, nullptr,
                nodes_t, ktrvtrb, nullptr, 512, CD, 0, 0);

            attn_tru<<<NTOK, 256>>>(qtrb, ktrvtrb, ktrr, vtrr, relay, zb);

            bn_fused_nc<<<256, 256>>>(zb, tr_bng + i * CD, tr_bnb + i * CD,
                                      rettb, 0, 1e-5f);

            gemm_nc<1><<<dim3(16, 7), 256>>>(tr_w1 + (size_t)i * DFFD * CD, tr_b1 + i * DFFD,
                                             rettb, htrb, nullptr, DFFD, CD);
            gemm_nc<2><<<dim3(4, 7), 256>>>(tr_w2 + (size_t)i * CD * DFFD, tr_b2 + i * CD,
                                            htrb, otrb, rettb, CD, DFFD);

            bn_fused_nc<<<256, 256>>>(otrb, tr_fg + i * CD, tr_fb + i * CD,
                                      relay, 1, 1e-5f);
        }
    }
}